// round 14
// baseline (speedup 1.0000x reference)
#include <cuda_runtime.h>
#include <cstdint>

#define N_RES   20000
#define N_EDGE  640000
#define NUM_AA  21
#define FEAT    340
#define EPSV    1e-8f
#define EPB     8          // edges (warps) per block

// ---------------- device scratch (no mallocs allowed) ----------------
// g_bb4[r*4+k] = atom k (n,ca,c,cb); atom0.w packs metadata:
//   int_as_float(seq*2 + noised)
__device__ float4 g_bb4[N_RES * 4];
// g_Rt4[r*4+c], c=0..2: column c of R = (R[0,c], R[1,c], R[2,c], 0)
//               c=3:    (t0, t1, t2, 0)
__device__ float4 g_Rt4[N_RES * 4];
__device__ float  g_local[N_RES * 12];  // R^T (bb - t)

__constant__ float c_freq[8] = {
    1.0f, 0.31622776601683794f, 0.1f, 0.03162277660168379f,
    0.01f, 0.0031622776601683794f, 0.001f, 0.00031622776601683794f
};

#define RBF_DELTA 1.0666666666666667f    /* (4/3)*0.8 */
#define RBF_DSQ   1.1377777777777778f    /* delta^2 */
#define RBF_C     0.10274027f            /* exp(-2*delta^2) */
#define RBF_C2    0.010555562f           /* RBF_C^2 */
#define PI_HALF   1.5707963267948966f

// ---------------- prep: mask dtype detection + residue geometry ----------------
// Mask dtype detection per-block from the first 512 words (= 2048 bytes,
// in-bounds under every interpretation of the 20000-element mask):
//   int32 0/1 mask   -> words all in {0,1}
//   float32 0/1 mask -> words all in {0, 0x3F800000}
//   packed bool      -> neither (P(ambiguous) = 8^-512 ~ 0)
__global__ void prep_kernel(const float* __restrict__ atom14,
                            const float* __restrict__ rig,
                            const int*   __restrict__ seq,
                            const void*  __restrict__ mask) {
    __shared__ int s_not01, s_notf;
    if (threadIdx.x == 0) { s_not01 = 0; s_notf = 0; }
    __syncthreads();
    {
        const unsigned int* mw = (const unsigned int*)mask;
        unsigned int v0 = mw[threadIdx.x];
        unsigned int v1 = mw[threadIdx.x + 256];
        int not01 = (v0 > 1u) | (v1 > 1u);
        int notf  = ((v0 != 0u && v0 != 0x3F800000u) ||
                     (v1 != 0u && v1 != 0x3F800000u));
        if (not01) atomicOr(&s_not01, 1);
        if (notf)  atomicOr(&s_notf, 1);
    }
    __syncthreads();
    int kind;                                // 0=bool(u8), 1=int32, 2=float32
    if (!s_notf)       kind = 2;
    else if (!s_not01) kind = 1;
    else               kind = 0;

    int r = blockIdx.x * blockDim.x + threadIdx.x;
    if (r >= N_RES) return;

    const float* a = atom14 + (size_t)r * 42;   // 14 atoms * 3
    float n0 = a[0], n1 = a[1], n2 = a[2];
    float ca0 = a[3], ca1 = a[4], ca2 = a[5];
    float c0 = a[6], c1 = a[7], c2 = a[8];

    float b0 = ca0 - n0, b1 = ca1 - n1, b2 = ca2 - n2;
    float e0 = c0 - ca0, e1 = c1 - ca1, e2 = c2 - ca2;
    float ax = b1 * e2 - b2 * e1;
    float ay = b2 * e0 - b0 * e2;
    float az = b0 * e1 - b1 * e0;
    float cb0 = -0.58273431f * ax + 0.56802827f * b0 - 0.54067466f * e0 + ca0;
    float cb1 = -0.58273431f * ay + 0.56802827f * b1 - 0.54067466f * e1 + ca1;
    float cb2 = -0.58273431f * az + 0.56802827f * b2 - 0.54067466f * e2 + ca2;

    int noised;
    if (kind == 0)      noised = ((const unsigned char*)mask)[r] ? 1 : 0;
    else if (kind == 1) noised = ((const int*)mask)[r] ? 1 : 0;
    else                noised = (((const float*)mask)[r] != 0.f) ? 1 : 0;

    float bb[12] = { n0, n1, n2, ca0, ca1, ca2, c0, c1, c2, cb0, cb1, cb2 };
    g_bb4[r * 4 + 0] = make_float4(n0, n1, n2, __int_as_float(seq[r] * 2 + noised));
    g_bb4[r * 4 + 1] = make_float4(ca0, ca1, ca2, 0.f);
    g_bb4[r * 4 + 2] = make_float4(c0, c1, c2, 0.f);
    g_bb4[r * 4 + 3] = make_float4(cb0, cb1, cb2, 0.f);

    const float* q = rig + (size_t)r * 7;
    float qw = q[0], qx = q[1], qy = q[2], qz = q[3];
    float inv = rsqrtf(qw * qw + qx * qx + qy * qy + qz * qz);
    qw *= inv; qx *= inv; qy *= inv; qz *= inv;

    float R[9];
    R[0] = 1.f - 2.f * (qy * qy + qz * qz);
    R[1] = 2.f * (qx * qy - qw * qz);
    R[2] = 2.f * (qx * qz + qw * qy);
    R[3] = 2.f * (qx * qy + qw * qz);
    R[4] = 1.f - 2.f * (qx * qx + qz * qz);
    R[5] = 2.f * (qy * qz - qw * qx);
    R[6] = 2.f * (qx * qz - qw * qy);
    R[7] = 2.f * (qy * qz + qw * qx);
    R[8] = 1.f - 2.f * (qx * qx + qy * qy);
    float t0 = q[4], t1 = q[5], t2 = q[6];

    // column-major chunks: chunk c = (R[0,c], R[1,c], R[2,c], 0); chunk 3 = t
    g_Rt4[r * 4 + 0] = make_float4(R[0], R[3], R[6], 0.f);
    g_Rt4[r * 4 + 1] = make_float4(R[1], R[4], R[7], 0.f);
    g_Rt4[r * 4 + 2] = make_float4(R[2], R[5], R[8], 0.f);
    g_Rt4[r * 4 + 3] = make_float4(t0, t1, t2, 0.f);

    // local[k][i] = sum_j R[j][i] * (bb[k][j] - t[j])
    #pragma unroll
    for (int k = 0; k < 4; k++) {
        float vx = bb[k * 3 + 0] - t0;
        float vy = bb[k * 3 + 1] - t1;
        float vz = bb[k * 3 + 2] - t2;
        #pragma unroll
        for (int i = 0; i < 3; i++) {
            g_local[r * 12 + k * 3 + i] = R[0 + i] * vx + R[3 + i] * vy + R[6 + i] * vz;
        }
    }
}

// ---------------- per-edge feature kernel: 1 warp / edge, zero smem ----------------
__global__ __launch_bounds__(EPB * 32) void edge_kernel(
    const int* __restrict__ eidx,     // [2, N_EDGE]: row0=dst, row1=src
    float* __restrict__ out) {

    const unsigned FULL = 0xFFFFFFFFu;
    int lane = threadIdx.x & 31;
    int e    = blockIdx.x * EPB + (threadIdx.x >> 5);

    int dst = eidx[e];
    int src = eidx[N_EDGE + e];

    // gather index plan:
    //   lanes 0-15 : RBF distance pair (src atom lane>>2, dst atom lane&3)
    //   lanes 20-31: region E element la = lane-20 (kk = la/3 dst atom,
    //                ii = la%3 R-column); lanes 16-19 duplicate la=0
    int la = min(max(lane - 20, 0), 11);
    int ekk = la / 3;                 // dst atom for region E
    int eii = la - 3 * ekk;           // R column for region E
    int ai_d = (lane < 16) ? (lane & 3) : ekk;       // f4d atom index
    int ci_r = (lane < 16) ? (lane & 3) : eii;       // f4rt chunk index

    // register gathers (broadcast-heavy, L2-resident tables)
    float4 f4s = g_bb4[src * 4 + ((lane >> 2) & 3)];
    float4 f4d = g_bb4[dst * 4 + ai_d];
    float4 f4rt = g_Rt4[src * 4 + ci_r];             // lane 3 holds t chunk
    float loc = g_local[src * 12 + min(lane, 11)];   // lanes 0-11 meaningful

    // metadata via 2 shuffles (lane 0 holds atom0 for both src and dst)
    int msrc = __float_as_int(__shfl_sync(FULL, f4s.w, 0));
    int mdst = __float_as_int(__shfl_sync(FULL, f4d.w, 0));
    float noised_src = (float)(msrc & 1);
    float noised_dst = (float)(mdst & 1);
    float keep_src = 1.f - noised_src;
    float keep_dst = 1.f - noised_dst;
    int hot_src = (msrc >> 1) + 2;     // one-hot pos within row, [2,22]
    int hot_dst = (mdst >> 1) + 23;    // one-hot pos within row, [23,43]

    float* __restrict__ row = out + (size_t)e * FEAT;

    // ---- region A: [0..43] flags + one-hots via 64-bit hot-mask ----
    if (lane < 11) {
        unsigned long long mask64 =
            ((unsigned long long)(keep_src != 0.f) << hot_src) |
            ((unsigned long long)(keep_dst != 0.f) << hot_dst);
        unsigned nib = (unsigned)(mask64 >> (4 * lane)) & 0xFu;
        float4 v4;
        v4.x = (nib & 1u) ? 1.f : 0.f;
        v4.y = (nib & 2u) ? 1.f : 0.f;
        v4.z = (nib & 4u) ? 1.f : 0.f;
        v4.w = (nib & 8u) ? 1.f : 0.f;
        if (lane == 0) { v4.x = noised_dst; v4.y = noised_src; }
        __stcs((float4*)(row + 4 * lane), v4);
    }

    // ---- region B: [44..299] RBF of 16 dists, 16 bins each ----
    // lanes 0-15 hold src atom (lane>>2) and dst atom (lane&3) in registers:
    // each computes its distance (MUFU.RSQ fast path); two dense STG.128
    // sweeps cover [44..171] and [172..299]. Bins via flattened geometric
    // recurrence (clamp 40 is value-exact: beyond it r0 == 0 in fp32).
    float dx = f4s.x - f4d.x + EPSV;
    float dy = f4s.y - f4d.y + EPSV;
    float dz = f4s.z - f4d.z + EPSV;
    float d2 = dx * dx + dy * dy + dz * dz;
    float D = rsqrtf(d2) * d2;              // sqrt via MUFU.RSQ + FMUL

    float mu0 = 2.0f + (float)(4 * (lane & 3)) * (20.0f / 15.0f);
    {
        // sweep 1: lane L -> floats [44+4L..47+4L], pair = L>>2, bins 4*(L&3)..+3
        float Da = __shfl_sync(FULL, D, lane >> 2);
        float z0 = (Da - mu0) * 0.8f;
        float r0 = __expf(-z0 * z0);
        float g1 = __expf(fminf(2.0f * RBF_DELTA * z0 - RBF_DSQ, 40.f));
        float g2 = g1 * g1 * RBF_C;
        float h  = g1 * RBF_C2;
        float r1 = r0 * g1;
        float r2 = r0 * g2;
        float r3 = r2 * h;
        __stcs((float4*)(row + 44 + 4 * lane), make_float4(r0, r1, r2, r3));

        // sweep 2: lane L -> floats [172+4L..175+4L], pair = 8 + (L>>2)
        float Db = __shfl_sync(FULL, D, 8 + (lane >> 2));
        z0 = (Db - mu0) * 0.8f;
        r0 = __expf(-z0 * z0);
        g1 = __expf(fminf(2.0f * RBF_DELTA * z0 - RBF_DSQ, 40.f));
        g2 = g1 * g1 * RBF_C;
        h  = g1 * RBF_C2;
        r1 = r0 * g1;
        r2 = r0 * g2;
        r3 = r2 * h;
        __stcs((float4*)(row + 172 + 4 * lane), make_float4(r0, r1, r2, r3));
    }

    // ---- region C: [300..315] positional enc, branchless: sin(x)=cos(x-pi/2) ----
    if (lane < 16) {
        float dp = (float)(dst - src);
        float bias = (lane < 8) ? 0.f : -PI_HALF;
        float ang = fmaf(dp, c_freq[lane & 7], bias);
        __stcs(row + 300 + lane, __cosf(ang));
    }

    // ---- regions D+E: [316..339] single predicated STG ----
    // lanes 0..11:  [316..327] src local frame (prefetched) * keep_src
    // lanes 20..31: [328..339] dst backbone in src frame * keep_dst
    //   acc = dot(R column eii, bb_dst[ekk] - t); R column + atom held locally,
    //   t shuffled from lane 3 (f4rt chunk 3).
    {
        float tx = __shfl_sync(FULL, f4rt.x, 3);
        float ty = __shfl_sync(FULL, f4rt.y, 3);
        float tz = __shfl_sync(FULL, f4rt.z, 3);
        float acc = f4rt.x * (f4d.x - tx)
                  + f4rt.y * (f4d.y - ty)
                  + f4rt.z * (f4d.z - tz);
        bool on = (lane < 12) | (lane >= 20);
        float v = (lane < 12) ? loc * keep_src : acc * keep_dst;
        int off = (lane < 12) ? (316 + lane) : (308 + lane);
        if (on) __stcs(row + off, v);
    }
}

// ---------------- launch ----------------
extern "C" void kernel_launch(void* const* d_in, const int* in_sizes, int n_in,
                              void* d_out, int out_size) {
    const float* atom14 = (const float*)d_in[0];
    const float* rigids = (const float*)d_in[1];
    const int*   seq    = (const int*)d_in[2];
    const void*  mask   = d_in[3];
    const int*   eidx   = (const int*)d_in[4];
    float* out = (float*)d_out;

    prep_kernel<<<(N_RES + 255) / 256, 256>>>(atom14, rigids, seq, mask);
    edge_kernel<<<N_EDGE / EPB, EPB * 32>>>(eidx, out);
}

// round 15
// speedup vs baseline: 1.0034x; 1.0034x over previous
#include <cuda_runtime.h>
#include <cstdint>

#define N_RES   20000
#define N_EDGE  640000
#define NUM_AA  21
#define FEAT    340
#define EPSV    1e-8f
#define EPB     8          // edges (warps) per block

// ---------------- device scratch (no mallocs allowed) ----------------
// One interleaved record per residue: 12 float4 (192 B)
//   [0..3]  bb atoms n, ca, c, cb   (atom0.w = int_as_float(seq*2 + noised))
//   [4..6]  R columns 0..2          (chunk c = (R[0,c], R[1,c], R[2,c], 0))
//   [7]     t                       (t0, t1, t2, 0)
//   [8..10] local frame: 12 floats  (R^T (bb - t))
//   [11]    pad
__device__ float4 g_all[N_RES * 12];

__constant__ float c_freq[8] = {
    1.0f, 0.31622776601683794f, 0.1f, 0.03162277660168379f,
    0.01f, 0.0031622776601683794f, 0.001f, 0.00031622776601683794f
};

#define RBF_DELTA 1.0666666666666667f    /* (4/3)*0.8 */
#define RBF_DSQ   1.1377777777777778f    /* delta^2 */
#define RBF_C     0.10274027f            /* exp(-2*delta^2) */
#define RBF_C2    0.010555562f           /* RBF_C^2 */
#define PI_HALF   1.5707963267948966f

// ---------------- prep: mask dtype detection + residue geometry ----------------
// Mask dtype detection per-block from the first 512 words (= 2048 bytes,
// in-bounds under every interpretation of the 20000-element mask):
//   int32 0/1 mask   -> words all in {0,1}
//   float32 0/1 mask -> words all in {0, 0x3F800000}
//   packed bool      -> neither (P(ambiguous) = 8^-512 ~ 0)
__global__ void prep_kernel(const float* __restrict__ atom14,
                            const float* __restrict__ rig,
                            const int*   __restrict__ seq,
                            const void*  __restrict__ mask) {
    __shared__ int s_not01, s_notf;
    if (threadIdx.x == 0) { s_not01 = 0; s_notf = 0; }
    __syncthreads();
    {
        const unsigned int* mw = (const unsigned int*)mask;
        unsigned int v0 = mw[threadIdx.x];
        unsigned int v1 = mw[threadIdx.x + 256];
        int not01 = (v0 > 1u) | (v1 > 1u);
        int notf  = ((v0 != 0u && v0 != 0x3F800000u) ||
                     (v1 != 0u && v1 != 0x3F800000u));
        if (not01) atomicOr(&s_not01, 1);
        if (notf)  atomicOr(&s_notf, 1);
    }
    __syncthreads();
    int kind;                                // 0=bool(u8), 1=int32, 2=float32
    if (!s_notf)       kind = 2;
    else if (!s_not01) kind = 1;
    else               kind = 0;

    int r = blockIdx.x * blockDim.x + threadIdx.x;
    if (r >= N_RES) return;

    const float* a = atom14 + (size_t)r * 42;   // 14 atoms * 3
    float n0 = a[0], n1 = a[1], n2 = a[2];
    float ca0 = a[3], ca1 = a[4], ca2 = a[5];
    float c0 = a[6], c1 = a[7], c2 = a[8];

    float b0 = ca0 - n0, b1 = ca1 - n1, b2 = ca2 - n2;
    float e0 = c0 - ca0, e1 = c1 - ca1, e2 = c2 - ca2;
    float ax = b1 * e2 - b2 * e1;
    float ay = b2 * e0 - b0 * e2;
    float az = b0 * e1 - b1 * e0;
    float cb0 = -0.58273431f * ax + 0.56802827f * b0 - 0.54067466f * e0 + ca0;
    float cb1 = -0.58273431f * ay + 0.56802827f * b1 - 0.54067466f * e1 + ca1;
    float cb2 = -0.58273431f * az + 0.56802827f * b2 - 0.54067466f * e2 + ca2;

    int noised;
    if (kind == 0)      noised = ((const unsigned char*)mask)[r] ? 1 : 0;
    else if (kind == 1) noised = ((const int*)mask)[r] ? 1 : 0;
    else                noised = (((const float*)mask)[r] != 0.f) ? 1 : 0;

    float bb[12] = { n0, n1, n2, ca0, ca1, ca2, c0, c1, c2, cb0, cb1, cb2 };
    float4* rec = g_all + (size_t)r * 12;
    rec[0] = make_float4(n0, n1, n2, __int_as_float(seq[r] * 2 + noised));
    rec[1] = make_float4(ca0, ca1, ca2, 0.f);
    rec[2] = make_float4(c0, c1, c2, 0.f);
    rec[3] = make_float4(cb0, cb1, cb2, 0.f);

    const float* q = rig + (size_t)r * 7;
    float qw = q[0], qx = q[1], qy = q[2], qz = q[3];
    float inv = rsqrtf(qw * qw + qx * qx + qy * qy + qz * qz);
    qw *= inv; qx *= inv; qy *= inv; qz *= inv;

    float R[9];
    R[0] = 1.f - 2.f * (qy * qy + qz * qz);
    R[1] = 2.f * (qx * qy - qw * qz);
    R[2] = 2.f * (qx * qz + qw * qy);
    R[3] = 2.f * (qx * qy + qw * qz);
    R[4] = 1.f - 2.f * (qx * qx + qz * qz);
    R[5] = 2.f * (qy * qz - qw * qx);
    R[6] = 2.f * (qx * qz - qw * qy);
    R[7] = 2.f * (qy * qz + qw * qx);
    R[8] = 1.f - 2.f * (qx * qx + qy * qy);
    float t0 = q[4], t1 = q[5], t2 = q[6];

    // column-major chunks: chunk c = (R[0,c], R[1,c], R[2,c], 0); chunk 3 = t
    rec[4] = make_float4(R[0], R[3], R[6], 0.f);
    rec[5] = make_float4(R[1], R[4], R[7], 0.f);
    rec[6] = make_float4(R[2], R[5], R[8], 0.f);
    rec[7] = make_float4(t0, t1, t2, 0.f);

    // local[k][i] = sum_j R[j][i] * (bb[k][j] - t[j]) -> rec[8..10]
    float lcl[12];
    #pragma unroll
    for (int k = 0; k < 4; k++) {
        float vx = bb[k * 3 + 0] - t0;
        float vy = bb[k * 3 + 1] - t1;
        float vz = bb[k * 3 + 2] - t2;
        #pragma unroll
        for (int i = 0; i < 3; i++) {
            lcl[k * 3 + i] = R[0 + i] * vx + R[3 + i] * vy + R[6 + i] * vz;
        }
    }
    rec[8]  = make_float4(lcl[0], lcl[1], lcl[2],  lcl[3]);
    rec[9]  = make_float4(lcl[4], lcl[5], lcl[6],  lcl[7]);
    rec[10] = make_float4(lcl[8], lcl[9], lcl[10], lcl[11]);
    rec[11] = make_float4(0.f, 0.f, 0.f, 0.f);
}

// ---------------- per-edge feature kernel: 1 warp / edge, zero smem ----------------
__global__ __launch_bounds__(EPB * 32) void edge_kernel(
    const int* __restrict__ eidx,     // [2, N_EDGE]: row0=dst, row1=src
    float* __restrict__ out) {

    const unsigned FULL = 0xFFFFFFFFu;
    int lane = threadIdx.x & 31;
    int e    = blockIdx.x * EPB + (threadIdx.x >> 5);

    int dst = eidx[e];
    int src = eidx[N_EDGE + e];

    // one base pointer per endpoint; all gathers are constant offsets off these
    const float4* bs = g_all + (size_t)src * 12;
    const float4* bd = g_all + (size_t)dst * 12;

    // gather index plan:
    //   lanes 0-15 : RBF distance pair (src atom lane>>2, dst atom lane&3)
    //   lanes 20-31: region E element la = lane-20 (kk = la/3 dst atom,
    //                ii = la%3 R-column); lanes 16-19 duplicate la=0
    int la = min(max(lane - 20, 0), 11);
    int ekk = la / 3;                 // dst atom for region E
    int eii = la - 3 * ekk;           // R column for region E
    int ai_d = (lane < 16) ? (lane & 3) : ekk;       // dst atom index
    int ci_r = (lane < 16) ? (lane & 3) : eii;       // R chunk index

    // register gathers (broadcast-heavy, L2-resident table)
    float4 f4s = bs[(lane >> 2) & 3];
    float4 f4d = bd[ai_d];
    float4 f4rt = bs[4 + ci_r];                      // lane 3 holds t chunk (4+3)
    float loc = ((const float*)(bs + 8))[min(lane, 11)];  // lanes 0-11 meaningful

    // metadata via 2 shuffles (lane 0 holds atom0 for both src and dst)
    int msrc = __float_as_int(__shfl_sync(FULL, f4s.w, 0));
    int mdst = __float_as_int(__shfl_sync(FULL, f4d.w, 0));
    float noised_src = (float)(msrc & 1);
    float noised_dst = (float)(mdst & 1);
    float keep_src = 1.f - noised_src;
    float keep_dst = 1.f - noised_dst;
    int hot_src = (msrc >> 1) + 2;     // one-hot pos within row, [2,22]
    int hot_dst = (mdst >> 1) + 23;    // one-hot pos within row, [23,43]

    float* __restrict__ row = out + (size_t)e * FEAT;

    // ---- region A: [0..43] flags + one-hots via 64-bit hot-mask ----
    if (lane < 11) {
        unsigned long long mask64 =
            ((unsigned long long)(keep_src != 0.f) << hot_src) |
            ((unsigned long long)(keep_dst != 0.f) << hot_dst);
        unsigned nib = (unsigned)(mask64 >> (4 * lane)) & 0xFu;
        float4 v4;
        v4.x = (nib & 1u) ? 1.f : 0.f;
        v4.y = (nib & 2u) ? 1.f : 0.f;
        v4.z = (nib & 4u) ? 1.f : 0.f;
        v4.w = (nib & 8u) ? 1.f : 0.f;
        if (lane == 0) { v4.x = noised_dst; v4.y = noised_src; }
        __stcs((float4*)(row + 4 * lane), v4);
    }

    // ---- region B: [44..299] RBF of 16 dists, 16 bins each ----
    // lanes 0-15 hold src atom (lane>>2) and dst atom (lane&3) in registers:
    // each computes its distance (MUFU.RSQ fast path); two dense STG.128
    // sweeps cover [44..171] and [172..299]. Bins via flattened geometric
    // recurrence (clamp 40 is value-exact: beyond it r0 == 0 in fp32).
    float dx = f4s.x - f4d.x + EPSV;
    float dy = f4s.y - f4d.y + EPSV;
    float dz = f4s.z - f4d.z + EPSV;
    float d2 = dx * dx + dy * dy + dz * dz;
    float D = rsqrtf(d2) * d2;              // sqrt via MUFU.RSQ + FMUL

    float mu0 = 2.0f + (float)(4 * (lane & 3)) * (20.0f / 15.0f);
    {
        // sweep 1: lane L -> floats [44+4L..47+4L], pair = L>>2, bins 4*(L&3)..+3
        float Da = __shfl_sync(FULL, D, lane >> 2);
        float z0 = (Da - mu0) * 0.8f;
        float r0 = __expf(-z0 * z0);
        float g1 = __expf(fminf(2.0f * RBF_DELTA * z0 - RBF_DSQ, 40.f));
        float g2 = g1 * g1 * RBF_C;
        float h  = g1 * RBF_C2;
        float r1 = r0 * g1;
        float r2 = r0 * g2;
        float r3 = r2 * h;
        __stcs((float4*)(row + 44 + 4 * lane), make_float4(r0, r1, r2, r3));

        // sweep 2: lane L -> floats [172+4L..175+4L], pair = 8 + (L>>2)
        float Db = __shfl_sync(FULL, D, 8 + (lane >> 2));
        z0 = (Db - mu0) * 0.8f;
        r0 = __expf(-z0 * z0);
        g1 = __expf(fminf(2.0f * RBF_DELTA * z0 - RBF_DSQ, 40.f));
        g2 = g1 * g1 * RBF_C;
        h  = g1 * RBF_C2;
        r1 = r0 * g1;
        r2 = r0 * g2;
        r3 = r2 * h;
        __stcs((float4*)(row + 172 + 4 * lane), make_float4(r0, r1, r2, r3));
    }

    // ---- region C: [300..315] positional enc, branchless: sin(x)=cos(x-pi/2) ----
    if (lane < 16) {
        float dp = (float)(dst - src);
        float bias = (lane < 8) ? 0.f : -PI_HALF;
        float ang = fmaf(dp, c_freq[lane & 7], bias);
        __stcs(row + 300 + lane, __cosf(ang));
    }

    // ---- regions D+E: [316..339] single predicated STG ----
    // lanes 0..11:  [316..327] src local frame (prefetched) * keep_src
    // lanes 20..31: [328..339] dst backbone in src frame * keep_dst
    //   acc = dot(R column eii, bb_dst[ekk] - t); R column + atom held locally,
    //   t shuffled from lane 3 (f4rt = chunk 4+3 there).
    {
        float tx = __shfl_sync(FULL, f4rt.x, 3);
        float ty = __shfl_sync(FULL, f4rt.y, 3);
        float tz = __shfl_sync(FULL, f4rt.z, 3);
        float acc = f4rt.x * (f4d.x - tx)
                  + f4rt.y * (f4d.y - ty)
                  + f4rt.z * (f4d.z - tz);
        bool on = (lane < 12) | (lane >= 20);
        float v = (lane < 12) ? loc * keep_src : acc * keep_dst;
        int off = (lane < 12) ? (316 + lane) : (308 + lane);
        if (on) __stcs(row + off, v);
    }
}

// ---------------- launch ----------------
extern "C" void kernel_launch(void* const* d_in, const int* in_sizes, int n_in,
                              void* d_out, int out_size) {
    const float* atom14 = (const float*)d_in[0];
    const float* rigids = (const float*)d_in[1];
    const int*   seq    = (const int*)d_in[2];
    const void*  mask   = d_in[3];
    const int*   eidx   = (const int*)d_in[4];
    float* out = (float*)d_out;

    prep_kernel<<<(N_RES + 255) / 256, 256>>>(atom14, rigids, seq, mask);
    edge_kernel<<<N_EDGE / EPB, EPB * 32>>>(eidx, out);
}